// round 16
// baseline (speedup 1.0000x reference)
#include <cuda_runtime.h>
#include <cuda_fp16.h>
#include <cstdint>
#include <cstddef>

// Problem constants
#define BB 16
#define LT 128
#define LV 4096
#define DD 1024
#define HH 16
#define HD 64
static constexpr float QSCALE = 0.125f;   // 64^-0.5
static constexpr float TSCALE = 65536.f;  // keeps Tf in fp16 normal range

// ===========================================================================
// Scratch (device globals) — all single fp16
// ===========================================================================
__device__ __half g_txf[(size_t)BB * LT * DD];
__device__ __half g_hdf[(size_t)BB * LV * DD];
__device__ __half g_Wt[4][(size_t)DD * DD];        // W^T fp16 (N,K)
__device__ float  g_bkv[2 * DD];
__device__ __half g_Qf[(size_t)BB * LT * DD];
__device__ __half g_Kf[(size_t)BB * LV * DD];
__device__ __half g_Vf[(size_t)BB * LV * DD];
__device__ __half g_Uf[(size_t)BB * HH * LT * LV]; // exp(S) unnormalized
__device__ float  g_Pp[(size_t)BB * HH * LT * 32]; // row partial sums (32 s-tiles)
__device__ float  g_scale[(size_t)BB * HH * LT];   // 2^16 / D^2
__device__ float  g_Tp[8][(size_t)BB * HH * LT * HD];
__device__ __half g_Tf[(size_t)BB * HH * LT * HD]; // Y/D^2 * 2^16
__device__ __half g_Of[(size_t)BB * LV * DD];

// ===========================================================================
// PTX helpers
// ===========================================================================
__device__ __forceinline__ uint32_t smem_u32(const void* p) {
    uint32_t a;
    asm("{ .reg .u64 t; cvta.to.shared.u64 t, %1; cvt.u32.u64 %0, t; }" : "=r"(a) : "l"(p));
    return a;
}
__device__ __forceinline__ void cp_async16(uint32_t dst, const void* src) {
    asm volatile("cp.async.cg.shared.global [%0], [%1], 16;" :: "r"(dst), "l"(src));
}
__device__ __forceinline__ void cp_commit() { asm volatile("cp.async.commit_group;"); }
template <int N>
__device__ __forceinline__ void cp_wait() { asm volatile("cp.async.wait_group %0;" :: "n"(N)); }

__device__ __forceinline__ void ldm_x4(uint32_t* r, uint32_t addr) {
    asm volatile("ldmatrix.sync.aligned.m8n8.x4.shared.b16 {%0,%1,%2,%3}, [%4];"
                 : "=r"(r[0]), "=r"(r[1]), "=r"(r[2]), "=r"(r[3]) : "r"(addr));
}
__device__ __forceinline__ void ldm_x4_t(uint32_t* r, uint32_t addr) {
    asm volatile("ldmatrix.sync.aligned.m8n8.x4.trans.shared.b16 {%0,%1,%2,%3}, [%4];"
                 : "=r"(r[0]), "=r"(r[1]), "=r"(r[2]), "=r"(r[3]) : "r"(addr));
}
// f32-accumulate mma
__device__ __forceinline__ void mma_h(float* c, const uint32_t* a, const uint32_t* b) {
    asm volatile(
        "mma.sync.aligned.m16n8k16.row.col.f32.f16.f16.f32 "
        "{%0,%1,%2,%3}, {%4,%5,%6,%7}, {%8,%9}, {%0,%1,%2,%3};"
        : "+f"(c[0]), "+f"(c[1]), "+f"(c[2]), "+f"(c[3])
        : "r"(a[0]), "r"(a[1]), "r"(a[2]), "r"(a[3]), "r"(b[0]), "r"(b[1]));
}
__device__ __forceinline__ void mma_hv(float* c, const uint32_t* a, uint32_t b0, uint32_t b1) {
    asm volatile(
        "mma.sync.aligned.m16n8k16.row.col.f32.f16.f16.f32 "
        "{%0,%1,%2,%3}, {%4,%5,%6,%7}, {%8,%9}, {%0,%1,%2,%3};"
        : "+f"(c[0]), "+f"(c[1]), "+f"(c[2]), "+f"(c[3])
        : "r"(a[0]), "r"(a[1]), "r"(a[2]), "r"(a[3]), "r"(b0), "r"(b1));
}
// f16-accumulate mma with zero C (single rounding of the k16 dot), fold to fp32
__device__ __forceinline__ void mma_h16acc(float* c, const uint32_t* a, const uint32_t* b) {
    uint32_t d0, d1;
    asm volatile(
        "mma.sync.aligned.m16n8k16.row.col.f16.f16.f16.f16 "
        "{%0,%1}, {%2,%3,%4,%5}, {%6,%7}, {%8,%9};"
        : "=r"(d0), "=r"(d1)
        : "r"(a[0]), "r"(a[1]), "r"(a[2]), "r"(a[3]), "r"(b[0]), "r"(b[1]),
          "r"(0u), "r"(0u));
    float2 f0 = __half22float2(*(__half2*)&d0);
    float2 f1 = __half22float2(*(__half2*)&d1);
    c[0] += f0.x; c[1] += f0.y;
    c[2] += f1.x; c[3] += f1.y;
}

// ===========================================================================
// fp32 -> fp16 convert
// ===========================================================================
__global__ __launch_bounds__(256) void conv_h(
    const float* __restrict__ in, __half* __restrict__ o, size_t n)
{
    size_t i = ((size_t)blockIdx.x * 256 + threadIdx.x) * 4;
    if (i >= n) return;
    float4 v = *(const float4*)(in + i);
    __half2* op = (__half2*)(o + i);
    op[0] = __halves2half2(__float2half_rn(v.x), __float2half_rn(v.y));
    op[1] = __halves2half2(__float2half_rn(v.z), __float2half_rn(v.w));
}

// ===========================================================================
// Weight transpose to fp16 + bias concat
// ===========================================================================
__global__ __launch_bounds__(256) void wtrans_h(
    const float* __restrict__ W, __half* __restrict__ Wt)
{
    __shared__ float t[32][33];
    int bx = blockIdx.x, by = blockIdx.y;
    int x = threadIdx.x, y = threadIdx.y;
#pragma unroll
    for (int i = 0; i < 32; i += 8)
        t[y + i][x] = W[(size_t)(by * 32 + y + i) * DD + bx * 32 + x];
    __syncthreads();
#pragma unroll
    for (int i = 0; i < 32; i += 8)
        Wt[(size_t)(bx * 32 + y + i) * DD + by * 32 + x] = __float2half_rn(t[x][y + i]);
}

__global__ __launch_bounds__(256) void concat_bias(
    const float* __restrict__ bk, const float* __restrict__ bv, float* __restrict__ b2)
{
    int i = blockIdx.x * 256 + threadIdx.x;
    if (i < DD) b2[i] = bk[i];
    else if (i < 2 * DD) b2[i] = bv[i - DD];
}

// ===========================================================================
// HMMA fp16 GEMM: tile 256x128, BK=64, 8 warps 4x2 (warp 64x64), 2-stage.
// OUTMODE 0: fp32 C.  2: fp16 single (Ch).  3: fp16 split KV (Ch=K, Cl=V).
// FACC 1: f16-accum mma (zero-C) folded into fp32 regs (2x tensor rate if
//         HMMA.f16 is double-rate vs f32-accum on this die).
// ===========================================================================
#define ROWB 144                        // 64 fp16 = 128 B + 16 pad
#define A_TILE (256 * ROWB)             // 36864
#define B_TILE (128 * ROWB)             // 18432
#define STAGE_B (A_TILE + B_TILE)       // 55296
#define SMEM_GEMM (2 * STAGE_B)         // 110592

template <int OUTMODE, int FACC>
__global__ __launch_bounds__(256, 1) void gemm_f16(
    const __half* __restrict__ A, const __half* __restrict__ B,
    const float* __restrict__ bias, float* __restrict__ C,
    __half* __restrict__ Ch, __half* __restrict__ Cl,
    int M, int N, int K, int lda, int ldb, int ldc, float alpha)
{
    extern __shared__ char smem[];
    const uint32_t sb = smem_u32(smem);
    const int tid = threadIdx.x;
    const int wid = tid >> 5, lane = tid & 31;
    const int m0 = blockIdx.y * 256, n0 = blockIdx.x * 128;
    const int wm = (wid >> 1) * 64;
    const int wn = (wid & 1) * 64;

    const char* gAp = (const char*)(A + (size_t)m0 * lda);
    const char* gBp = (const char*)(B + (size_t)n0 * ldb);

    float acc[4][8][4];
#pragma unroll
    for (int i = 0; i < 4; i++)
#pragma unroll
        for (int j = 0; j < 8; j++)
#pragma unroll
            for (int k = 0; k < 4; k++) acc[i][j][k] = 0.f;

    const int NT = K / 64;

    auto issue = [&](int kt, int s) {
        const uint32_t st0 = sb + s * STAGE_B;
        const char* gA = gAp + (size_t)kt * 128;
        const char* gB = gBp + (size_t)kt * 128;
        const int ldab = lda * 2, ldbb = ldb * 2;
#pragma unroll
        for (int i = 0; i < 8; i++) {           // A: 2048 chunks
            int id = tid + i * 256;
            int r = id >> 3, c = id & 7;
            cp_async16(st0 + r * ROWB + c * 16, gA + (size_t)r * ldab + c * 16);
        }
#pragma unroll
        for (int i = 0; i < 4; i++) {           // B: 1024 chunks
            int id = tid + i * 256;
            int r = id >> 3, c = id & 7;
            cp_async16(st0 + A_TILE + r * ROWB + c * 16, gB + (size_t)r * ldbb + c * 16);
        }
        cp_commit();
    };

    issue(0, 0);

    for (int kt = 0; kt < NT; kt++) {
        if (kt + 1 < NT) { issue(kt + 1, (kt + 1) & 1); cp_wait<1>(); }
        else cp_wait<0>();
        __syncthreads();

        const uint32_t st0 = sb + (kt & 1) * STAGE_B;
        const uint32_t Afs = st0;
        const uint32_t Bfs = st0 + A_TILE;

#pragma unroll
        for (int ks = 0; ks < 4; ks++) {
            const int k16 = ks * 16;
            uint32_t af[4][4];
#pragma unroll
            for (int mi = 0; mi < 4; mi++) {
                int row = wm + mi * 16 + (lane & 15);
                int col = k16 + ((lane >> 4) << 3);
                ldm_x4(af[mi], Afs + row * ROWB + col * 2);
            }
            uint32_t bf[4][4];
#pragma unroll
            for (int bi = 0; bi < 4; bi++) {
                int nrow = wn + bi * 16 + (lane & 7) + ((lane >> 4) << 3);
                int col = k16 + (((lane >> 3) & 1) << 3);
                ldm_x4(bf[bi], Bfs + nrow * ROWB + col * 2);
            }
#pragma unroll
            for (int mi = 0; mi < 4; mi++)
#pragma unroll
                for (int nb = 0; nb < 8; nb++) {
                    if (FACC) mma_h16acc(acc[mi][nb], af[mi], &bf[nb >> 1][(nb & 1) * 2]);
                    else      mma_h(acc[mi][nb], af[mi], &bf[nb >> 1][(nb & 1) * 2]);
                }
        }
        __syncthreads();
    }

    const int gid = lane >> 2, tig = lane & 3;
    __half* dst3 = (OUTMODE == 3) ? ((n0 < DD) ? Ch : Cl) : Ch;
    const int nbase = (OUTMODE == 3 && n0 >= DD) ? n0 - DD : n0;

#pragma unroll
    for (int mi = 0; mi < 4; mi++) {
        int r0 = m0 + wm + mi * 16 + gid;
#pragma unroll
        for (int nb = 0; nb < 8; nb++) {
            int c = n0 + wn + nb * 8 + tig * 2;
            float b0 = __ldg(&bias[c]), b1 = __ldg(&bias[c + 1]);
            float v00 = alpha * (acc[mi][nb][0] + b0);
            float v01 = alpha * (acc[mi][nb][1] + b1);
            float v10 = alpha * (acc[mi][nb][2] + b0);
            float v11 = alpha * (acc[mi][nb][3] + b1);
            if (OUTMODE == 0) {
                *(float2*)(C + (size_t)r0 * ldc + c) = make_float2(v00, v01);
                *(float2*)(C + (size_t)(r0 + 8) * ldc + c) = make_float2(v10, v11);
            } else {
                int cl = nbase + wn + nb * 8 + tig * 2;
                *(__half2*)(dst3 + (size_t)r0 * DD + cl) =
                    __halves2half2(__float2half_rn(v00), __float2half_rn(v01));
                *(__half2*)(dst3 + (size_t)(r0 + 8) * DD + cl) =
                    __halves2half2(__float2half_rn(v10), __float2half_rn(v11));
            }
        }
    }
}

// ===========================================================================
// Scores + exp fused (per batch-range): grid (LV/128, HH, nb), b += boff
// ===========================================================================
#define SROWB 144
#define STILE (128 * SROWB)
#define SMEM_SC (2 * STILE)            // 36864

__global__ __launch_bounds__(256) void attn_scores_exp(
    const __half* __restrict__ Qf, const __half* __restrict__ Kf,
    __half* __restrict__ Uf, float* __restrict__ Pp, int boff)
{
    extern __shared__ char smem[];
    const uint32_t sb = smem_u32(smem);
    const int st = blockIdx.x, h = blockIdx.y, b = blockIdx.z + boff;
    const int tid = threadIdx.x;
    const int wid = tid >> 5, lane = tid & 31;
    const int wm = (wid >> 1) * 32, wn = (wid & 1) * 64;

    const char* gp[2] = {
        (const char*)(Qf + ((size_t)b * LT) * DD + h * HD),
        (const char*)(Kf + ((size_t)b * LV + st * 128) * DD + h * HD) };

#pragma unroll
    for (int i = 0; i < 8; i++) {
        int id = tid + i * 256;
        int t = id >> 10, r = (id >> 3) & 127, c = id & 7;
        cp_async16(sb + t * STILE + r * SROWB + c * 16,
                   gp[t] + (size_t)r * DD * 2 + c * 16);
    }
    cp_commit();
    cp_wait<0>();
    __syncthreads();

    float acc[2][8][4];
#pragma unroll
    for (int i = 0; i < 2; i++)
#pragma unroll
        for (int j = 0; j < 8; j++)
#pragma unroll
            for (int k = 0; k < 4; k++) acc[i][j][k] = 0.f;

    const uint32_t Afs = sb, Bfs = sb + STILE;

#pragma unroll
    for (int ks = 0; ks < 4; ks++) {
        const int k16 = ks * 16;
        uint32_t af[2][4];
#pragma unroll
        for (int mi = 0; mi < 2; mi++) {
            int row = wm + mi * 16 + (lane & 15);
            int col = k16 + ((lane >> 4) << 3);
            ldm_x4(af[mi], Afs + row * SROWB + col * 2);
        }
        uint32_t bf[4][4];
#pragma unroll
        for (int bi = 0; bi < 4; bi++) {
            int nrow = wn + bi * 16 + (lane & 7) + ((lane >> 4) << 3);
            int col = k16 + (((lane >> 3) & 1) << 3);
            ldm_x4(bf[bi], Bfs + nrow * SROWB + col * 2);
        }
#pragma unroll
        for (int mi = 0; mi < 2; mi++)
#pragma unroll
            for (int nb = 0; nb < 8; nb++)
                mma_h(acc[mi][nb], af[mi], &bf[nb >> 1][(nb & 1) * 2]);
    }

    __half* Ub = Uf + ((size_t)(b * HH + h) * LT) * LV + st * 128;
    const int gid = lane >> 2, tig = lane & 3;
    float ls[4] = {0.f, 0.f, 0.f, 0.f};
#pragma unroll
    for (int mi = 0; mi < 2; mi++) {
        int r0 = wm + mi * 16 + gid;
#pragma unroll
        for (int nb = 0; nb < 8; nb++) {
            int c = wn + nb * 8 + tig * 2;
            float u00 = __expf(acc[mi][nb][0]);
            float u01 = __expf(acc[mi][nb][1]);
            float u10 = __expf(acc[mi][nb][2]);
            float u11 = __expf(acc[mi][nb][3]);
            ls[mi * 2 + 0] += u00 + u01;
            ls[mi * 2 + 1] += u10 + u11;
            *(__half2*)(Ub + (size_t)r0 * LV + c) =
                __halves2half2(__float2half_rn(u00), __float2half_rn(u01));
            *(__half2*)(Ub + (size_t)(r0 + 8) * LV + c) =
                __halves2half2(__float2half_rn(u10), __float2half_rn(u11));
        }
    }
#pragma unroll
    for (int j = 0; j < 4; j++) {
        ls[j] += __shfl_xor_sync(0xFFFFFFFF, ls[j], 1);
        ls[j] += __shfl_xor_sync(0xFFFFFFFF, ls[j], 2);
    }
    __syncthreads();
    float* sums = (float*)smem;      // [128][2]
    if (tig == 0) {
#pragma unroll
        for (int j = 0; j < 4; j++) {
            int mi = j >> 1, half = j & 1;
            int row = wm + mi * 16 + gid + 8 * half;
            sums[row * 2 + (wid & 1)] = ls[j];
        }
    }
    __syncthreads();
    if (tid < 128) {
        float d = sums[tid * 2] + sums[tid * 2 + 1];
        Pp[(((size_t)(b * HH + h) * LT) + tid) * 32 + st] = d;
    }
}

// ===========================================================================
// Row scale: scale = 2^16 / D^2
// ===========================================================================
__global__ __launch_bounds__(256) void reduce_scale(
    const float* __restrict__ Pp, float* __restrict__ scale)
{
    int r = blockIdx.x * 256 + threadIdx.x;
    float d = 0.f;
#pragma unroll
    for (int j = 0; j < 32; j++) d += Pp[(size_t)r * 32 + j];
    scale[r] = TSCALE / (d * d);
}

// ===========================================================================
// PV: Ypart = Uf[128t, 512s] @ Vf[512s, 64d]. grid (8, HH, nb), b += boff
// ===========================================================================
#define PV_AROW 80
#define PV_ATILE (128 * PV_AROW)        // 10240
#define PV_BROW 144
#define PV_BTILE (32 * PV_BROW)         // 4608
#define PV_STAGE (PV_ATILE + PV_BTILE)  // 14848
#define SMEM_PV (2 * PV_STAGE)          // 29696

__global__ __launch_bounds__(256) void attn_pv_mma(
    const __half* __restrict__ Uf, const __half* __restrict__ Vf,
    float* __restrict__ Tp, int boff)
{
    extern __shared__ char smem[];
    const uint32_t sb = smem_u32(smem);
    const int seg = blockIdx.x, h = blockIdx.y, b = blockIdx.z + boff;
    const int tid = threadIdx.x;
    const int wid = tid >> 5, lane = tid & 31;
    const int wm = (wid >> 1) * 32, wn = (wid & 1) * 32;

    const char* pA = (const char*)(Uf + ((size_t)(b * HH + h) * LT) * LV + seg * 512);
    const char* pB = (const char*)(Vf + ((size_t)b * LV + seg * 512) * DD + h * HD);

    auto issue = [&](int kt, int s) {
        const uint32_t st0 = sb + s * PV_STAGE;
#pragma unroll
        for (int i = 0; i < 2; i++) {
            int id = tid + i * 256;
            int r = id >> 2, c = id & 3;
            cp_async16(st0 + r * PV_AROW + c * 16,
                       pA + (size_t)r * LV * 2 + (size_t)kt * 64 + c * 16);
        }
        {
            int r = tid >> 3, c = tid & 7;
            cp_async16(st0 + PV_ATILE + r * PV_BROW + c * 16,
                       pB + ((size_t)kt * 32 + r) * DD * 2 + c * 16);
        }
        cp_commit();
    };

    float acc[2][4][4];
#pragma unroll
    for (int i = 0; i < 2; i++)
#pragma unroll
        for (int j = 0; j < 4; j++)
#pragma unroll
            for (int k = 0; k < 4; k++) acc[i][j][k] = 0.f;

    issue(0, 0);
    for (int kt = 0; kt < 16; kt++) {
        if (kt + 1 < 16) { issue(kt + 1, (kt + 1) & 1); cp_wait<1>(); }
        else cp_wait<0>();
        __syncthreads();

        const uint32_t st0 = sb + (kt & 1) * PV_STAGE;
        const uint32_t Aus = st0, Bfs = st0 + PV_ATILE;

#pragma unroll
        for (int ks = 0; ks < 2; ks++) {
            const int k16 = ks * 16;
            uint32_t au[2][4];
#pragma unroll
            for (int mi = 0; mi < 2; mi++) {
                int row = wm + mi * 16 + (lane & 15);
                int col = k16 + ((lane >> 4) << 3);
                ldm_x4(au[mi], Aus + row * PV_AROW + col * 2);
            }
            uint32_t bf[2][4];
#pragma unroll
            for (int bi = 0; bi < 2; bi++) {
                int srow = k16 + ((lane >> 4) << 3) + (lane & 7);
                int dcol = wn + bi * 16 + (((lane >> 3) & 1) << 3);
                ldm_x4_t(bf[bi], Bfs + srow * PV_BROW + dcol * 2);
            }
#pragma unroll
            for (int mi = 0; mi < 2; mi++)
#pragma unroll
                for (int nb = 0; nb < 4; nb++) {
                    const int bi = nb >> 1, j = nb & 1;
                    mma_hv(acc[mi][nb], au[mi], bf[bi][j], bf[bi][j + 2]);
                }
        }
        __syncthreads();
    }

    float* Tb = Tp + (size_t)seg * (BB * HH * LT * HD) + ((size_t)(b * HH + h) * LT) * HD;
    const int gid = lane >> 2, tig = lane & 3;
#pragma unroll
    for (int mi = 0; mi < 2; mi++) {
        int r0 = wm + mi * 16 + gid;
#pragma unroll
        for (int nb = 0; nb < 4; nb++) {
            int c = wn + nb * 8 + tig * 2;
            *(float2*)(Tb + (size_t)r0 * HD + c) = make_float2(acc[mi][nb][0], acc[mi][nb][1]);
            *(float2*)(Tb + (size_t)(r0 + 8) * HD + c) = make_float2(acc[mi][nb][2], acc[mi][nb][3]);
        }
    }
}

// reduce partials + apply 2^16/D^2 (pointer-offset for halves)
__global__ __launch_bounds__(256) void reduce_T(
    const float* __restrict__ Tp, const float* __restrict__ scale,
    __half* __restrict__ Tf)
{
    size_t i = (size_t)blockIdx.x * 256 + threadIdx.x;
    float s = 0.f;
#pragma unroll
    for (int g = 0; g < 8; g++) s += Tp[(size_t)g * (BB * HH * LT * HD) + i];
    Tf[i] = __float2half_rn(s * scale[i >> 6]);
}

// ===========================================================================
// OUT: O[128s, 64d] = 2^-16 * U^T @ Tf. grid (LV/128, HH, nb), b += boff
// ===========================================================================
#define AO_AROW 272
#define AO_ATILE (32 * AO_AROW)         // 8704
#define AO_BROW 144
#define AO_BTILE (32 * AO_BROW)         // 4608
#define AO_STAGE (AO_ATILE + AO_BTILE)  // 13312
#define SMEM_AO (2 * AO_STAGE)          // 26624

__global__ __launch_bounds__(256) void attn_out_mma(
    const __half* __restrict__ Uf, const __half* __restrict__ Tf,
    __half* __restrict__ Of, int boff)
{
    extern __shared__ char smem[];
    const uint32_t sb = smem_u32(smem);
    const int st = blockIdx.x, h = blockIdx.y, b = blockIdx.z + boff;
    const int tid = threadIdx.x;
    const int wid = tid >> 5, lane = tid & 31;
    const int wm = (wid >> 1) * 32, wn = (wid & 1) * 32;

    const char* pA = (const char*)(Uf + ((size_t)(b * HH + h) * LT) * LV + st * 128);
    const char* pB = (const char*)(Tf + ((size_t)(b * HH + h) * LT) * HD);

    auto issue = [&](int kt, int s) {
        const uint32_t st0 = sb + s * AO_STAGE;
#pragma unroll
        for (int i = 0; i < 2; i++) {
            int id = tid + i * 256;
            int r = id >> 4, c = id & 15;
            cp_async16(st0 + r * AO_AROW + c * 16,
                       pA + ((size_t)kt * 32 + r) * LV * 2 + c * 16);
        }
        {
            int r = tid >> 3, c = tid & 7;
            cp_async16(st0 + AO_ATILE + r * AO_BROW + c * 16,
                       pB + ((size_t)kt * 32 + r) * HD * 2 + c * 16);
        }
        cp_commit();
    };

    float acc[2][4][4];
#pragma unroll
    for (int i = 0; i < 2; i++)
#pragma unroll
        for (int j = 0; j < 4; j++)
#pragma unroll
            for (int k = 0; k < 4; k++) acc[i][j][k] = 0.f;

    issue(0, 0);
    for (int kt = 0; kt < 4; kt++) {
        if (kt + 1 < 4) { issue(kt + 1, (kt + 1) & 1); cp_wait<1>(); }
        else cp_wait<0>();
        __syncthreads();

        const uint32_t st0 = sb + (kt & 1) * AO_STAGE;
        const uint32_t Aus = st0, Bfs = st0 + AO_ATILE;

#pragma unroll
        for (int ks = 0; ks < 2; ks++) {
            const int k16 = ks * 16;
            uint32_t au[2][4];
#pragma unroll
            for (int mi = 0; mi < 2; mi++) {
                int trow = k16 + ((lane >> 4) << 3) + (lane & 7);
                int scol = wm + mi * 16 + (((lane >> 3) & 1) << 3);
                ldm_x4_t(au[mi], Aus + trow * AO_AROW + scol * 2);
            }
            uint32_t bf[2][4];
#pragma unroll
            for (int bi = 0; bi < 2; bi++) {
                int trow = k16 + ((lane >> 4) << 3) + (lane & 7);
                int dcol = wn + bi * 16 + (((lane >> 3) & 1) << 3);
                ldm_x4_t(bf[bi], Bfs + trow * AO_BROW + dcol * 2);
            }
#pragma unroll
            for (int mi = 0; mi < 2; mi++)
#pragma unroll
                for (int nb = 0; nb < 4; nb++) {
                    const int bi = nb >> 1, j = nb & 1;
                    mma_hv(acc[mi][nb], au[mi], bf[bi][j], bf[bi][j + 2]);
                }
        }
        __syncthreads();
    }

    const float inv = 1.f / TSCALE;
    const int gid = lane >> 2, tig = lane & 3;
#pragma unroll
    for (int mi = 0; mi < 2; mi++) {
        int srow = st * 128 + wm + mi * 16 + gid;
#pragma unroll
        for (int nb = 0; nb < 4; nb++) {
            int c = h * HD + wn + nb * 8 + tig * 2;
            size_t o0 = ((size_t)b * LV + srow) * DD + c;
            size_t o1 = ((size_t)b * LV + srow + 8) * DD + c;
            *(__half2*)(Of + o0) = __halves2half2(
                __float2half_rn(acc[mi][nb][0] * inv), __float2half_rn(acc[mi][nb][1] * inv));
            *(__half2*)(Of + o1) = __halves2half2(
                __float2half_rn(acc[mi][nb][2] * inv), __float2half_rn(acc[mi][nb][3] * inv));
        }
    }
}

// ===========================================================================
// Launch — R14 2-stream schedule; KV + O-proj use f16-accum GEMM
// ===========================================================================
extern "C" void kernel_launch(void* const* d_in, const int* in_sizes, int n_in,
                              void* d_out, int out_size)
{
    const float* hidden = (const float*)d_in[0];
    const float* text   = (const float*)d_in[1];
    const float* Wq = (const float*)d_in[2];
    const float* bq = (const float*)d_in[3];
    const float* Wk = (const float*)d_in[4];
    const float* bk = (const float*)d_in[5];
    const float* Wv = (const float*)d_in[6];
    const float* bv = (const float*)d_in[7];
    const float* Wo = (const float*)d_in[8];
    const float* bo = (const float*)d_in[9];
    float* out = (float*)d_out;

    __half *txf, *hdf, *Wt, *Qf, *Kf, *Vf, *Uf, *Tf, *Of;
    float *Pp, *scl, *Tp, *bkv;
    cudaGetSymbolAddress((void**)&txf, g_txf);
    cudaGetSymbolAddress((void**)&hdf, g_hdf);
    cudaGetSymbolAddress((void**)&Wt, g_Wt);
    cudaGetSymbolAddress((void**)&bkv, g_bkv);
    cudaGetSymbolAddress((void**)&Qf, g_Qf);
    cudaGetSymbolAddress((void**)&Kf, g_Kf);
    cudaGetSymbolAddress((void**)&Vf, g_Vf);
    cudaGetSymbolAddress((void**)&Uf, g_Uf);
    cudaGetSymbolAddress((void**)&Pp, g_Pp);
    cudaGetSymbolAddress((void**)&scl, g_scale);
    cudaGetSymbolAddress((void**)&Tp, g_Tp);
    cudaGetSymbolAddress((void**)&Tf, g_Tf);
    cudaGetSymbolAddress((void**)&Of, g_Of);

    cudaFuncSetAttribute((const void*)gemm_f16<0, 1>, cudaFuncAttributeMaxDynamicSharedMemorySize, SMEM_GEMM);
    cudaFuncSetAttribute((const void*)gemm_f16<2, 0>, cudaFuncAttributeMaxDynamicSharedMemorySize, SMEM_GEMM);
    cudaFuncSetAttribute((const void*)gemm_f16<3, 1>, cudaFuncAttributeMaxDynamicSharedMemorySize, SMEM_GEMM);
    cudaFuncSetAttribute(attn_scores_exp, cudaFuncAttributeMaxDynamicSharedMemorySize, SMEM_SC);
    cudaFuncSetAttribute(attn_pv_mma, cudaFuncAttributeMaxDynamicSharedMemorySize, SMEM_PV);
    cudaFuncSetAttribute(attn_out_mma, cudaFuncAttributeMaxDynamicSharedMemorySize, SMEM_AO);

    const size_t WSZ = (size_t)DD * DD;
    const int HB = BB / 2;                         // half batch
    const size_t HROW = (size_t)HB * HH * LT;      // softmax rows per half
    const size_t HVD  = (size_t)HB * LV * DD;      // elems per half
    const size_t HTHD = HROW * HD;                 // T elems per half

    cudaStream_t s0 = 0, sB;
    cudaStreamCreateWithFlags(&sB, cudaStreamNonBlocking);
    cudaEvent_t evFork, evQ, evKV1, evKV2, evAO1, evAO2;
    cudaEventCreateWithFlags(&evFork, cudaEventDisableTiming);
    cudaEventCreateWithFlags(&evQ,    cudaEventDisableTiming);
    cudaEventCreateWithFlags(&evKV1,  cudaEventDisableTiming);
    cudaEventCreateWithFlags(&evKV2,  cudaEventDisableTiming);
    cudaEventCreateWithFlags(&evAO1,  cudaEventDisableTiming);
    cudaEventCreateWithFlags(&evAO2,  cudaEventDisableTiming);

    // ---- fork sB from s0 ----
    cudaEventRecord(evFork, s0);
    cudaStreamWaitEvent(sB, evFork, 0);

    // ---- sB: text path (Q projection, f32-accum) + Wo transpose ----
    dim3 wt(32, 32);
    conv_h<<<(BB * LT * DD) / 1024, 256, 0, sB>>>(text, txf, (size_t)BB * LT * DD);
    wtrans_h<<<wt, dim3(32, 8), 0, sB>>>(Wq, Wt + 0 * WSZ);
    gemm_f16<2, 0><<<dim3(DD / 128, (BB * LT) / 256), 256, SMEM_GEMM, sB>>>(
        txf, Wt + 0 * WSZ, bq, nullptr, Qf, nullptr,
        BB * LT, DD, DD, DD, DD, DD, QSCALE);
    wtrans_h<<<wt, dim3(32, 8), 0, sB>>>(Wo, Wt + 3 * WSZ);
    cudaEventRecord(evQ, sB);

    // ---- s0: hidden path + KV GEMM halves (f16-accum) ----
    conv_h<<<(BB * LV * DD) / 1024, 256, 0, s0>>>(hidden, hdf, (size_t)BB * LV * DD);
    wtrans_h<<<wt, dim3(32, 8), 0, s0>>>(Wk, Wt + 1 * WSZ);
    wtrans_h<<<wt, dim3(32, 8), 0, s0>>>(Wv, Wt + 2 * WSZ);
    concat_bias<<<8, 256, 0, s0>>>(bk, bv, bkv);

    gemm_f16<3, 1><<<dim3(2 * DD / 128, (HB * LV) / 256), 256, SMEM_GEMM, s0>>>(
        hdf, Wt + 1 * WSZ, bkv, nullptr, Kf, Vf,
        HB * LV, 2 * DD, DD, DD, DD, DD, 1.0f);
    cudaEventRecord(evKV1, s0);
    gemm_f16<3, 1><<<dim3(2 * DD / 128, (HB * LV) / 256), 256, SMEM_GEMM, s0>>>(
        hdf + HVD, Wt + 1 * WSZ, bkv, nullptr, Kf + HVD, Vf + HVD,
        HB * LV, 2 * DD, DD, DD, DD, DD, 1.0f);
    cudaEventRecord(evKV2, s0);

    // ---- sB: attention half 1 (overlaps KV half 2) ----
    cudaStreamWaitEvent(sB, evKV1, 0);
    attn_scores_exp<<<dim3(LV / 128, HH, HB), 256, SMEM_SC, sB>>>(Qf, Kf, Uf, Pp, 0);
    reduce_scale<<<HROW / 256, 256, 0, sB>>>(Pp, scl);
    attn_pv_mma<<<dim3(8, HH, HB), 256, SMEM_PV, sB>>>(Uf, Vf, Tp, 0);
    reduce_T<<<HTHD / 256, 256, 0, sB>>>(Tp, scl, Tf);
    attn_out_mma<<<dim3(LV / 128, HH, HB), 256, SMEM_AO, sB>>>(Uf, Tf, Of, 0);
    cudaEventRecord(evAO1, sB);

    // ---- sB: attention half 2 (overlaps O-proj half 1) ----
    cudaStreamWaitEvent(sB, evKV2, 0);
    attn_scores_exp<<<dim3(LV / 128, HH, HB), 256, SMEM_SC, sB>>>(Qf, Kf, Uf, Pp, HB);
    reduce_scale<<<HROW / 256, 256, 0, sB>>>(Pp + HROW * 32, scl + HROW);
    attn_pv_mma<<<dim3(8, HH, HB), 256, SMEM_PV, sB>>>(Uf, Vf, Tp, HB);
    reduce_T<<<HTHD / 256, 256, 0, sB>>>(Tp + HTHD, scl + HROW, Tf + HTHD);
    attn_out_mma<<<dim3(LV / 128, HH, HB), 256, SMEM_AO, sB>>>(Uf, Tf, Of, HB);
    cudaEventRecord(evAO2, sB);

    // ---- s0: output projection halves (f16-accum) ----
    cudaStreamWaitEvent(s0, evQ, 0);
    cudaStreamWaitEvent(s0, evAO1, 0);
    gemm_f16<0, 1><<<dim3(DD / 128, (HB * LV) / 256), 256, SMEM_GEMM, s0>>>(
        Of, Wt + 3 * WSZ, bo, out, nullptr, nullptr,
        HB * LV, DD, DD, DD, DD, DD, 1.0f);
    cudaStreamWaitEvent(s0, evAO2, 0);
    gemm_f16<0, 1><<<dim3(DD / 128, (HB * LV) / 256), 256, SMEM_GEMM, s0>>>(
        Of + HVD, Wt + 3 * WSZ, bo, out + HVD, nullptr, nullptr,
        HB * LV, DD, DD, DD, DD, DD, 1.0f);
    // sB joined into s0 via evAO2.
}

// round 17
// speedup vs baseline: 1.4183x; 1.4183x over previous
#include <cuda_runtime.h>
#include <cuda_fp16.h>
#include <cstdint>
#include <cstddef>

// Problem constants
#define BB 16
#define LT 128
#define LV 4096
#define DD 1024
#define HH 16
#define HD 64
static constexpr float QSCALE = 0.125f;   // 64^-0.5
static constexpr float TSCALE = 65536.f;  // keeps Tf in fp16 normal range

// ===========================================================================
// Scratch (device globals) — all single fp16
// ===========================================================================
__device__ __half g_txf[(size_t)BB * LT * DD];
__device__ __half g_hdf[(size_t)BB * LV * DD];
__device__ __half g_Wt[4][(size_t)DD * DD];        // W^T fp16 (N,K)
__device__ float  g_bkv[2 * DD];
__device__ __half g_Qf[(size_t)BB * LT * DD];
__device__ __half g_Kf[(size_t)BB * LV * DD];
__device__ __half g_Vf[(size_t)BB * LV * DD];
__device__ __half g_Uf[(size_t)BB * HH * LT * LV]; // exp(S) unnormalized
__device__ float  g_Pp[(size_t)BB * HH * LT * 32]; // row partial sums (32 s-tiles)
__device__ float  g_scale[(size_t)BB * HH * LT];   // 2^16 / D^2
__device__ float  g_Tp[8][(size_t)BB * HH * LT * HD];
__device__ __half g_Tf[(size_t)BB * HH * LT * HD]; // Y/D^2 * 2^16
__device__ __half g_Of[(size_t)BB * LV * DD];

// ===========================================================================
// PTX helpers
// ===========================================================================
__device__ __forceinline__ uint32_t smem_u32(const void* p) {
    uint32_t a;
    asm("{ .reg .u64 t; cvta.to.shared.u64 t, %1; cvt.u32.u64 %0, t; }" : "=r"(a) : "l"(p));
    return a;
}
__device__ __forceinline__ void cp_async16(uint32_t dst, const void* src) {
    asm volatile("cp.async.cg.shared.global [%0], [%1], 16;" :: "r"(dst), "l"(src));
}
__device__ __forceinline__ void cp_commit() { asm volatile("cp.async.commit_group;"); }
template <int N>
__device__ __forceinline__ void cp_wait() { asm volatile("cp.async.wait_group %0;" :: "n"(N)); }

__device__ __forceinline__ void ldm_x4(uint32_t* r, uint32_t addr) {
    asm volatile("ldmatrix.sync.aligned.m8n8.x4.shared.b16 {%0,%1,%2,%3}, [%4];"
                 : "=r"(r[0]), "=r"(r[1]), "=r"(r[2]), "=r"(r[3]) : "r"(addr));
}
__device__ __forceinline__ void ldm_x4_t(uint32_t* r, uint32_t addr) {
    asm volatile("ldmatrix.sync.aligned.m8n8.x4.trans.shared.b16 {%0,%1,%2,%3}, [%4];"
                 : "=r"(r[0]), "=r"(r[1]), "=r"(r[2]), "=r"(r[3]) : "r"(addr));
}
__device__ __forceinline__ void mma_h(float* c, const uint32_t* a, const uint32_t* b) {
    asm volatile(
        "mma.sync.aligned.m16n8k16.row.col.f32.f16.f16.f32 "
        "{%0,%1,%2,%3}, {%4,%5,%6,%7}, {%8,%9}, {%0,%1,%2,%3};"
        : "+f"(c[0]), "+f"(c[1]), "+f"(c[2]), "+f"(c[3])
        : "r"(a[0]), "r"(a[1]), "r"(a[2]), "r"(a[3]), "r"(b[0]), "r"(b[1]));
}
__device__ __forceinline__ void mma_hv(float* c, const uint32_t* a, uint32_t b0, uint32_t b1) {
    asm volatile(
        "mma.sync.aligned.m16n8k16.row.col.f32.f16.f16.f32 "
        "{%0,%1,%2,%3}, {%4,%5,%6,%7}, {%8,%9}, {%0,%1,%2,%3};"
        : "+f"(c[0]), "+f"(c[1]), "+f"(c[2]), "+f"(c[3])
        : "r"(a[0]), "r"(a[1]), "r"(a[2]), "r"(a[3]), "r"(b0), "r"(b1));
}

// ===========================================================================
// fp32 -> fp16 convert
// ===========================================================================
__global__ __launch_bounds__(256) void conv_h(
    const float* __restrict__ in, __half* __restrict__ o, size_t n)
{
    size_t i = ((size_t)blockIdx.x * 256 + threadIdx.x) * 4;
    if (i >= n) return;
    float4 v = *(const float4*)(in + i);
    __half2* op = (__half2*)(o + i);
    op[0] = __halves2half2(__float2half_rn(v.x), __float2half_rn(v.y));
    op[1] = __halves2half2(__float2half_rn(v.z), __float2half_rn(v.w));
}

// ===========================================================================
// Paired weight transpose to fp16: blockIdx.z selects (W0->T0) or (W1->T1)
// ===========================================================================
__global__ __launch_bounds__(256) void wtrans_h2(
    const float* __restrict__ W0, const float* __restrict__ W1,
    __half* __restrict__ T0, __half* __restrict__ T1)
{
    __shared__ float t[32][33];
    const float* W = blockIdx.z ? W1 : W0;
    __half* Wt = blockIdx.z ? T1 : T0;
    int bx = blockIdx.x, by = blockIdx.y;
    int x = threadIdx.x, y = threadIdx.y;
#pragma unroll
    for (int i = 0; i < 32; i += 8)
        t[y + i][x] = W[(size_t)(by * 32 + y + i) * DD + bx * 32 + x];
    __syncthreads();
#pragma unroll
    for (int i = 0; i < 32; i += 8)
        Wt[(size_t)(bx * 32 + y + i) * DD + by * 32 + x] = __float2half_rn(t[x][y + i]);
}

__global__ __launch_bounds__(256) void concat_bias(
    const float* __restrict__ bk, const float* __restrict__ bv, float* __restrict__ b2)
{
    int i = blockIdx.x * 256 + threadIdx.x;
    if (i < DD) b2[i] = bk[i];
    else if (i < 2 * DD) b2[i] = bv[i - DD];
}

// ===========================================================================
// HMMA fp16 GEMM (R9/R14 config): tile 256x128, BK=64, 8 warps 4x2
// (warp 64x64), 2-stage cp.async, 256 threads.
// OUTMODE 0: fp32 C.  2: fp16 single (Ch).  3: fp16 split KV (Ch=K, Cl=V).
// ===========================================================================
#define ROWB 144                        // 64 fp16 = 128 B + 16 pad
#define A_TILE (256 * ROWB)             // 36864
#define B_TILE (128 * ROWB)             // 18432
#define STAGE_B (A_TILE + B_TILE)       // 55296
#define SMEM_GEMM (2 * STAGE_B)         // 110592

template <int OUTMODE>
__global__ __launch_bounds__(256, 1) void gemm_f16(
    const __half* __restrict__ A, const __half* __restrict__ B,
    const float* __restrict__ bias, float* __restrict__ C,
    __half* __restrict__ Ch, __half* __restrict__ Cl,
    int M, int N, int K, int lda, int ldb, int ldc, float alpha)
{
    extern __shared__ char smem[];
    const uint32_t sb = smem_u32(smem);
    const int tid = threadIdx.x;
    const int wid = tid >> 5, lane = tid & 31;
    const int m0 = blockIdx.y * 256, n0 = blockIdx.x * 128;
    const int wm = (wid >> 1) * 64;
    const int wn = (wid & 1) * 64;

    const char* gAp = (const char*)(A + (size_t)m0 * lda);
    const char* gBp = (const char*)(B + (size_t)n0 * ldb);

    float acc[4][8][4];
#pragma unroll
    for (int i = 0; i < 4; i++)
#pragma unroll
        for (int j = 0; j < 8; j++)
#pragma unroll
            for (int k = 0; k < 4; k++) acc[i][j][k] = 0.f;

    const int NT = K / 64;

    auto issue = [&](int kt, int s) {
        const uint32_t st0 = sb + s * STAGE_B;
        const char* gA = gAp + (size_t)kt * 128;
        const char* gB = gBp + (size_t)kt * 128;
        const int ldab = lda * 2, ldbb = ldb * 2;
#pragma unroll
        for (int i = 0; i < 8; i++) {           // A: 2048 chunks
            int id = tid + i * 256;
            int r = id >> 3, c = id & 7;
            cp_async16(st0 + r * ROWB + c * 16, gA + (size_t)r * ldab + c * 16);
        }
#pragma unroll
        for (int i = 0; i < 4; i++) {           // B: 1024 chunks
            int id = tid + i * 256;
            int r = id >> 3, c = id & 7;
            cp_async16(st0 + A_TILE + r * ROWB + c * 16, gB + (size_t)r * ldbb + c * 16);
        }
        cp_commit();
    };

    issue(0, 0);

    for (int kt = 0; kt < NT; kt++) {
        if (kt + 1 < NT) { issue(kt + 1, (kt + 1) & 1); cp_wait<1>(); }
        else cp_wait<0>();
        __syncthreads();

        const uint32_t st0 = sb + (kt & 1) * STAGE_B;
        const uint32_t Afs = st0;
        const uint32_t Bfs = st0 + A_TILE;

#pragma unroll
        for (int ks = 0; ks < 4; ks++) {
            const int k16 = ks * 16;
            uint32_t af[4][4];
#pragma unroll
            for (int mi = 0; mi < 4; mi++) {
                int row = wm + mi * 16 + (lane & 15);
                int col = k16 + ((lane >> 4) << 3);
                ldm_x4(af[mi], Afs + row * ROWB + col * 2);
            }
            uint32_t bf[4][4];
#pragma unroll
            for (int bi = 0; bi < 4; bi++) {
                int nrow = wn + bi * 16 + (lane & 7) + ((lane >> 4) << 3);
                int col = k16 + (((lane >> 3) & 1) << 3);
                ldm_x4(bf[bi], Bfs + nrow * ROWB + col * 2);
            }
#pragma unroll
            for (int mi = 0; mi < 4; mi++)
#pragma unroll
                for (int nb = 0; nb < 8; nb++)
                    mma_h(acc[mi][nb], af[mi], &bf[nb >> 1][(nb & 1) * 2]);
        }
        __syncthreads();
    }

    const int gid = lane >> 2, tig = lane & 3;
    __half* dst3 = (OUTMODE == 3) ? ((n0 < DD) ? Ch : Cl) : Ch;
    const int nbase = (OUTMODE == 3 && n0 >= DD) ? n0 - DD : n0;

#pragma unroll
    for (int mi = 0; mi < 4; mi++) {
        int r0 = m0 + wm + mi * 16 + gid;
#pragma unroll
        for (int nb = 0; nb < 8; nb++) {
            int c = n0 + wn + nb * 8 + tig * 2;
            float b0 = __ldg(&bias[c]), b1 = __ldg(&bias[c + 1]);
            float v00 = alpha * (acc[mi][nb][0] + b0);
            float v01 = alpha * (acc[mi][nb][1] + b1);
            float v10 = alpha * (acc[mi][nb][2] + b0);
            float v11 = alpha * (acc[mi][nb][3] + b1);
            if (OUTMODE == 0) {
                *(float2*)(C + (size_t)r0 * ldc + c) = make_float2(v00, v01);
                *(float2*)(C + (size_t)(r0 + 8) * ldc + c) = make_float2(v10, v11);
            } else {
                int cl = nbase + wn + nb * 8 + tig * 2;
                *(__half2*)(dst3 + (size_t)r0 * DD + cl) =
                    __halves2half2(__float2half_rn(v00), __float2half_rn(v01));
                *(__half2*)(dst3 + (size_t)(r0 + 8) * DD + cl) =
                    __halves2half2(__float2half_rn(v10), __float2half_rn(v11));
            }
        }
    }
}

// ===========================================================================
// Scores + exp fused (per batch-range): grid (LV/128, HH, nb), b += boff
// ===========================================================================
#define SROWB 144
#define STILE (128 * SROWB)
#define SMEM_SC (2 * STILE)            // 36864

__global__ __launch_bounds__(256) void attn_scores_exp(
    const __half* __restrict__ Qf, const __half* __restrict__ Kf,
    __half* __restrict__ Uf, float* __restrict__ Pp, int boff)
{
    extern __shared__ char smem[];
    const uint32_t sb = smem_u32(smem);
    const int st = blockIdx.x, h = blockIdx.y, b = blockIdx.z + boff;
    const int tid = threadIdx.x;
    const int wid = tid >> 5, lane = tid & 31;
    const int wm = (wid >> 1) * 32, wn = (wid & 1) * 64;

    const char* gp[2] = {
        (const char*)(Qf + ((size_t)b * LT) * DD + h * HD),
        (const char*)(Kf + ((size_t)b * LV + st * 128) * DD + h * HD) };

#pragma unroll
    for (int i = 0; i < 8; i++) {
        int id = tid + i * 256;
        int t = id >> 10, r = (id >> 3) & 127, c = id & 7;
        cp_async16(sb + t * STILE + r * SROWB + c * 16,
                   gp[t] + (size_t)r * DD * 2 + c * 16);
    }
    cp_commit();
    cp_wait<0>();
    __syncthreads();

    float acc[2][8][4];
#pragma unroll
    for (int i = 0; i < 2; i++)
#pragma unroll
        for (int j = 0; j < 8; j++)
#pragma unroll
            for (int k = 0; k < 4; k++) acc[i][j][k] = 0.f;

    const uint32_t Afs = sb, Bfs = sb + STILE;

#pragma unroll
    for (int ks = 0; ks < 4; ks++) {
        const int k16 = ks * 16;
        uint32_t af[2][4];
#pragma unroll
        for (int mi = 0; mi < 2; mi++) {
            int row = wm + mi * 16 + (lane & 15);
            int col = k16 + ((lane >> 4) << 3);
            ldm_x4(af[mi], Afs + row * SROWB + col * 2);
        }
        uint32_t bf[4][4];
#pragma unroll
        for (int bi = 0; bi < 4; bi++) {
            int nrow = wn + bi * 16 + (lane & 7) + ((lane >> 4) << 3);
            int col = k16 + (((lane >> 3) & 1) << 3);
            ldm_x4(bf[bi], Bfs + nrow * SROWB + col * 2);
        }
#pragma unroll
        for (int mi = 0; mi < 2; mi++)
#pragma unroll
            for (int nb = 0; nb < 8; nb++)
                mma_h(acc[mi][nb], af[mi], &bf[nb >> 1][(nb & 1) * 2]);
    }

    __half* Ub = Uf + ((size_t)(b * HH + h) * LT) * LV + st * 128;
    const int gid = lane >> 2, tig = lane & 3;
    float ls[4] = {0.f, 0.f, 0.f, 0.f};
#pragma unroll
    for (int mi = 0; mi < 2; mi++) {
        int r0 = wm + mi * 16 + gid;
#pragma unroll
        for (int nb = 0; nb < 8; nb++) {
            int c = wn + nb * 8 + tig * 2;
            float u00 = __expf(acc[mi][nb][0]);
            float u01 = __expf(acc[mi][nb][1]);
            float u10 = __expf(acc[mi][nb][2]);
            float u11 = __expf(acc[mi][nb][3]);
            ls[mi * 2 + 0] += u00 + u01;
            ls[mi * 2 + 1] += u10 + u11;
            *(__half2*)(Ub + (size_t)r0 * LV + c) =
                __halves2half2(__float2half_rn(u00), __float2half_rn(u01));
            *(__half2*)(Ub + (size_t)(r0 + 8) * LV + c) =
                __halves2half2(__float2half_rn(u10), __float2half_rn(u11));
        }
    }
#pragma unroll
    for (int j = 0; j < 4; j++) {
        ls[j] += __shfl_xor_sync(0xFFFFFFFF, ls[j], 1);
        ls[j] += __shfl_xor_sync(0xFFFFFFFF, ls[j], 2);
    }
    __syncthreads();
    float* sums = (float*)smem;      // [128][2]
    if (tig == 0) {
#pragma unroll
        for (int j = 0; j < 4; j++) {
            int mi = j >> 1, half = j & 1;
            int row = wm + mi * 16 + gid + 8 * half;
            sums[row * 2 + (wid & 1)] = ls[j];
        }
    }
    __syncthreads();
    if (tid < 128) {
        float d = sums[tid * 2] + sums[tid * 2 + 1];
        Pp[(((size_t)(b * HH + h) * LT) + tid) * 32 + st] = d;
    }
}

// ===========================================================================
// Row scale: scale = 2^16 / D^2
// ===========================================================================
__global__ __launch_bounds__(256) void reduce_scale(
    const float* __restrict__ Pp, float* __restrict__ scale)
{
    int r = blockIdx.x * 256 + threadIdx.x;
    float d = 0.f;
#pragma unroll
    for (int j = 0; j < 32; j++) d += Pp[(size_t)r * 32 + j];
    scale[r] = TSCALE / (d * d);
}

// ===========================================================================
// PV: Ypart = Uf[128t, 512s] @ Vf[512s, 64d]. grid (8, HH, nb), b += boff
// ===========================================================================
#define PV_AROW 80
#define PV_ATILE (128 * PV_AROW)        // 10240
#define PV_BROW 144
#define PV_BTILE (32 * PV_BROW)         // 4608
#define PV_STAGE (PV_ATILE + PV_BTILE)  // 14848
#define SMEM_PV (2 * PV_STAGE)          // 29696

__global__ __launch_bounds__(256) void attn_pv_mma(
    const __half* __restrict__ Uf, const __half* __restrict__ Vf,
    float* __restrict__ Tp, int boff)
{
    extern __shared__ char smem[];
    const uint32_t sb = smem_u32(smem);
    const int seg = blockIdx.x, h = blockIdx.y, b = blockIdx.z + boff;
    const int tid = threadIdx.x;
    const int wid = tid >> 5, lane = tid & 31;
    const int wm = (wid >> 1) * 32, wn = (wid & 1) * 32;

    const char* pA = (const char*)(Uf + ((size_t)(b * HH + h) * LT) * LV + seg * 512);
    const char* pB = (const char*)(Vf + ((size_t)b * LV + seg * 512) * DD + h * HD);

    auto issue = [&](int kt, int s) {
        const uint32_t st0 = sb + s * PV_STAGE;
#pragma unroll
        for (int i = 0; i < 2; i++) {
            int id = tid + i * 256;
            int r = id >> 2, c = id & 3;
            cp_async16(st0 + r * PV_AROW + c * 16,
                       pA + (size_t)r * LV * 2 + (size_t)kt * 64 + c * 16);
        }
        {
            int r = tid >> 3, c = tid & 7;
            cp_async16(st0 + PV_ATILE + r * PV_BROW + c * 16,
                       pB + ((size_t)kt * 32 + r) * DD * 2 + c * 16);
        }
        cp_commit();
    };

    float acc[2][4][4];
#pragma unroll
    for (int i = 0; i < 2; i++)
#pragma unroll
        for (int j = 0; j < 4; j++)
#pragma unroll
            for (int k = 0; k < 4; k++) acc[i][j][k] = 0.f;

    issue(0, 0);
    for (int kt = 0; kt < 16; kt++) {
        if (kt + 1 < 16) { issue(kt + 1, (kt + 1) & 1); cp_wait<1>(); }
        else cp_wait<0>();
        __syncthreads();

        const uint32_t st0 = sb + (kt & 1) * PV_STAGE;
        const uint32_t Aus = st0, Bfs = st0 + PV_ATILE;

#pragma unroll
        for (int ks = 0; ks < 2; ks++) {
            const int k16 = ks * 16;
            uint32_t au[2][4];
#pragma unroll
            for (int mi = 0; mi < 2; mi++) {
                int row = wm + mi * 16 + (lane & 15);
                int col = k16 + ((lane >> 4) << 3);
                ldm_x4(au[mi], Aus + row * PV_AROW + col * 2);
            }
            uint32_t bf[2][4];
#pragma unroll
            for (int bi = 0; bi < 2; bi++) {
                int srow = k16 + ((lane >> 4) << 3) + (lane & 7);
                int dcol = wn + bi * 16 + (((lane >> 3) & 1) << 3);
                ldm_x4_t(bf[bi], Bfs + srow * PV_BROW + dcol * 2);
            }
#pragma unroll
            for (int mi = 0; mi < 2; mi++)
#pragma unroll
                for (int nb = 0; nb < 4; nb++) {
                    const int bi = nb >> 1, j = nb & 1;
                    mma_hv(acc[mi][nb], au[mi], bf[bi][j], bf[bi][j + 2]);
                }
        }
        __syncthreads();
    }

    float* Tb = Tp + (size_t)seg * (BB * HH * LT * HD) + ((size_t)(b * HH + h) * LT) * HD;
    const int gid = lane >> 2, tig = lane & 3;
#pragma unroll
    for (int mi = 0; mi < 2; mi++) {
        int r0 = wm + mi * 16 + gid;
#pragma unroll
        for (int nb = 0; nb < 4; nb++) {
            int c = wn + nb * 8 + tig * 2;
            *(float2*)(Tb + (size_t)r0 * HD + c) = make_float2(acc[mi][nb][0], acc[mi][nb][1]);
            *(float2*)(Tb + (size_t)(r0 + 8) * HD + c) = make_float2(acc[mi][nb][2], acc[mi][nb][3]);
        }
    }
}

// reduce partials + apply 2^16/D^2 (pointer-offset for halves)
__global__ __launch_bounds__(256) void reduce_T(
    const float* __restrict__ Tp, const float* __restrict__ scale,
    __half* __restrict__ Tf)
{
    size_t i = (size_t)blockIdx.x * 256 + threadIdx.x;
    float s = 0.f;
#pragma unroll
    for (int g = 0; g < 8; g++) s += Tp[(size_t)g * (BB * HH * LT * HD) + i];
    Tf[i] = __float2half_rn(s * scale[i >> 6]);
}

// ===========================================================================
// OUT: O[128s, 64d] = 2^-16 * U^T @ Tf. grid (LV/128, HH, nb), b += boff
// ===========================================================================
#define AO_AROW 272
#define AO_ATILE (32 * AO_AROW)         // 8704
#define AO_BROW 144
#define AO_BTILE (32 * AO_BROW)         // 4608
#define AO_STAGE (AO_ATILE + AO_BTILE)  // 13312
#define SMEM_AO (2 * AO_STAGE)          // 26624

__global__ __launch_bounds__(256) void attn_out_mma(
    const __half* __restrict__ Uf, const __half* __restrict__ Tf,
    __half* __restrict__ Of, int boff)
{
    extern __shared__ char smem[];
    const uint32_t sb = smem_u32(smem);
    const int st = blockIdx.x, h = blockIdx.y, b = blockIdx.z + boff;
    const int tid = threadIdx.x;
    const int wid = tid >> 5, lane = tid & 31;
    const int wm = (wid >> 1) * 32, wn = (wid & 1) * 32;

    const char* pA = (const char*)(Uf + ((size_t)(b * HH + h) * LT) * LV + st * 128);
    const char* pB = (const char*)(Tf + ((size_t)(b * HH + h) * LT) * HD);

    auto issue = [&](int kt, int s) {
        const uint32_t st0 = sb + s * AO_STAGE;
#pragma unroll
        for (int i = 0; i < 2; i++) {
            int id = tid + i * 256;
            int r = id >> 4, c = id & 15;
            cp_async16(st0 + r * AO_AROW + c * 16,
                       pA + ((size_t)kt * 32 + r) * LV * 2 + c * 16);
        }
        {
            int r = tid >> 3, c = tid & 7;
            cp_async16(st0 + AO_ATILE + r * AO_BROW + c * 16,
                       pB + ((size_t)kt * 32 + r) * HD * 2 + c * 16);
        }
        cp_commit();
    };

    float acc[2][4][4];
#pragma unroll
    for (int i = 0; i < 2; i++)
#pragma unroll
        for (int j = 0; j < 4; j++)
#pragma unroll
            for (int k = 0; k < 4; k++) acc[i][j][k] = 0.f;

    issue(0, 0);
    for (int kt = 0; kt < 4; kt++) {
        if (kt + 1 < 4) { issue(kt + 1, (kt + 1) & 1); cp_wait<1>(); }
        else cp_wait<0>();
        __syncthreads();

        const uint32_t st0 = sb + (kt & 1) * AO_STAGE;
        const uint32_t Aus = st0, Bfs = st0 + AO_ATILE;

#pragma unroll
        for (int ks = 0; ks < 2; ks++) {
            const int k16 = ks * 16;
            uint32_t au[2][4];
#pragma unroll
            for (int mi = 0; mi < 2; mi++) {
                int trow = k16 + ((lane >> 4) << 3) + (lane & 7);
                int scol = wm + mi * 16 + (((lane >> 3) & 1) << 3);
                ldm_x4_t(au[mi], Aus + trow * AO_AROW + scol * 2);
            }
            uint32_t bf[2][4];
#pragma unroll
            for (int bi = 0; bi < 2; bi++) {
                int trow = k16 + ((lane >> 4) << 3) + (lane & 7);
                int dcol = wn + bi * 16 + (((lane >> 3) & 1) << 3);
                ldm_x4_t(bf[bi], Bfs + trow * AO_BROW + dcol * 2);
            }
#pragma unroll
            for (int mi = 0; mi < 2; mi++)
#pragma unroll
                for (int nb = 0; nb < 4; nb++) {
                    const int bi = nb >> 1, j = nb & 1;
                    mma_hv(acc[mi][nb], au[mi], bf[bi][j], bf[bi][j + 2]);
                }
        }
        __syncthreads();
    }

    const float inv = 1.f / TSCALE;
    const int gid = lane >> 2, tig = lane & 3;
#pragma unroll
    for (int mi = 0; mi < 2; mi++) {
        int srow = st * 128 + wm + mi * 16 + gid;
#pragma unroll
        for (int nb = 0; nb < 4; nb++) {
            int c = h * HD + wn + nb * 8 + tig * 2;
            size_t o0 = ((size_t)b * LV + srow) * DD + c;
            size_t o1 = ((size_t)b * LV + srow + 8) * DD + c;
            *(__half2*)(Of + o0) = __halves2half2(
                __float2half_rn(acc[mi][nb][0] * inv), __float2half_rn(acc[mi][nb][1] * inv));
            *(__half2*)(Of + o1) = __halves2half2(
                __float2half_rn(acc[mi][nb][2] * inv), __float2half_rn(acc[mi][nb][3] * inv));
        }
    }
}

// ===========================================================================
// Launch — R14 2-stream batch-halved pipeline (paired weight transposes)
// ===========================================================================
extern "C" void kernel_launch(void* const* d_in, const int* in_sizes, int n_in,
                              void* d_out, int out_size)
{
    const float* hidden = (const float*)d_in[0];
    const float* text   = (const float*)d_in[1];
    const float* Wq = (const float*)d_in[2];
    const float* bq = (const float*)d_in[3];
    const float* Wk = (const float*)d_in[4];
    const float* bk = (const float*)d_in[5];
    const float* Wv = (const float*)d_in[6];
    const float* bv = (const float*)d_in[7];
    const float* Wo = (const float*)d_in[8];
    const float* bo = (const float*)d_in[9];
    float* out = (float*)d_out;

    __half *txf, *hdf, *Wt, *Qf, *Kf, *Vf, *Uf, *Tf, *Of;
    float *Pp, *scl, *Tp, *bkv;
    cudaGetSymbolAddress((void**)&txf, g_txf);
    cudaGetSymbolAddress((void**)&hdf, g_hdf);
    cudaGetSymbolAddress((void**)&Wt, g_Wt);
    cudaGetSymbolAddress((void**)&bkv, g_bkv);
    cudaGetSymbolAddress((void**)&Qf, g_Qf);
    cudaGetSymbolAddress((void**)&Kf, g_Kf);
    cudaGetSymbolAddress((void**)&Vf, g_Vf);
    cudaGetSymbolAddress((void**)&Uf, g_Uf);
    cudaGetSymbolAddress((void**)&Pp, g_Pp);
    cudaGetSymbolAddress((void**)&scl, g_scale);
    cudaGetSymbolAddress((void**)&Tp, g_Tp);
    cudaGetSymbolAddress((void**)&Tf, g_Tf);
    cudaGetSymbolAddress((void**)&Of, g_Of);

    cudaFuncSetAttribute(gemm_f16<0>, cudaFuncAttributeMaxDynamicSharedMemorySize, SMEM_GEMM);
    cudaFuncSetAttribute(gemm_f16<2>, cudaFuncAttributeMaxDynamicSharedMemorySize, SMEM_GEMM);
    cudaFuncSetAttribute(gemm_f16<3>, cudaFuncAttributeMaxDynamicSharedMemorySize, SMEM_GEMM);
    cudaFuncSetAttribute(attn_scores_exp, cudaFuncAttributeMaxDynamicSharedMemorySize, SMEM_SC);
    cudaFuncSetAttribute(attn_pv_mma, cudaFuncAttributeMaxDynamicSharedMemorySize, SMEM_PV);
    cudaFuncSetAttribute(attn_out_mma, cudaFuncAttributeMaxDynamicSharedMemorySize, SMEM_AO);

    const size_t WSZ = (size_t)DD * DD;
    const int HB = BB / 2;                         // half batch
    const size_t HROW = (size_t)HB * HH * LT;      // softmax rows per half
    const size_t HVD  = (size_t)HB * LV * DD;      // elems per half (Kf/Vf/Of)
    const size_t HTHD = HROW * HD;                 // T elems per half

    cudaStream_t s0 = 0, sB;
    cudaStreamCreateWithFlags(&sB, cudaStreamNonBlocking);
    cudaEvent_t evFork, evQ, evKV1, evKV2, evAO1, evAO2;
    cudaEventCreateWithFlags(&evFork, cudaEventDisableTiming);
    cudaEventCreateWithFlags(&evQ,    cudaEventDisableTiming);
    cudaEventCreateWithFlags(&evKV1,  cudaEventDisableTiming);
    cudaEventCreateWithFlags(&evKV2,  cudaEventDisableTiming);
    cudaEventCreateWithFlags(&evAO1,  cudaEventDisableTiming);
    cudaEventCreateWithFlags(&evAO2,  cudaEventDisableTiming);

    // ---- fork sB from s0 ----
    cudaEventRecord(evFork, s0);
    cudaStreamWaitEvent(sB, evFork, 0);

    // ---- sB: text path (Q projection) + paired Wq/Wo transpose ----
    dim3 wt2(32, 32, 2);
    conv_h<<<(BB * LT * DD) / 1024, 256, 0, sB>>>(text, txf, (size_t)BB * LT * DD);
    wtrans_h2<<<wt2, dim3(32, 8), 0, sB>>>(Wq, Wo, Wt + 0 * WSZ, Wt + 3 * WSZ);
    gemm_f16<2><<<dim3(DD / 128, (BB * LT) / 256), 256, SMEM_GEMM, sB>>>(
        txf, Wt + 0 * WSZ, bq, nullptr, Qf, nullptr,
        BB * LT, DD, DD, DD, DD, DD, QSCALE);
    cudaEventRecord(evQ, sB);

    // ---- s0: hidden path + KV GEMM halves ----
    conv_h<<<(BB * LV * DD) / 1024, 256, 0, s0>>>(hidden, hdf, (size_t)BB * LV * DD);
    concat_bias<<<8, 256, 0, s0>>>(bk, bv, bkv);
    wtrans_h2<<<wt2, dim3(32, 8), 0, s0>>>(Wk, Wv, Wt + 1 * WSZ, Wt + 2 * WSZ);

    gemm_f16<3><<<dim3(2 * DD / 128, (HB * LV) / 256), 256, SMEM_GEMM, s0>>>(
        hdf, Wt + 1 * WSZ, bkv, nullptr, Kf, Vf,
        HB * LV, 2 * DD, DD, DD, DD, DD, 1.0f);
    cudaEventRecord(evKV1, s0);
    gemm_f16<3><<<dim3(2 * DD / 128, (HB * LV) / 256), 256, SMEM_GEMM, s0>>>(
        hdf + HVD, Wt + 1 * WSZ, bkv, nullptr, Kf + HVD, Vf + HVD,
        HB * LV, 2 * DD, DD, DD, DD, DD, 1.0f);
    cudaEventRecord(evKV2, s0);

    // ---- sB: attention half 1 (overlaps KV half 2) ----
    cudaStreamWaitEvent(sB, evKV1, 0);
    attn_scores_exp<<<dim3(LV / 128, HH, HB), 256, SMEM_SC, sB>>>(Qf, Kf, Uf, Pp, 0);
    reduce_scale<<<HROW / 256, 256, 0, sB>>>(Pp, scl);
    attn_pv_mma<<<dim3(8, HH, HB), 256, SMEM_PV, sB>>>(Uf, Vf, Tp, 0);
    reduce_T<<<HTHD / 256, 256, 0, sB>>>(Tp, scl, Tf);
    attn_out_mma<<<dim3(LV / 128, HH, HB), 256, SMEM_AO, sB>>>(Uf, Tf, Of, 0);
    cudaEventRecord(evAO1, sB);

    // ---- sB: attention half 2 (overlaps O-proj half 1 on s0) ----
    cudaStreamWaitEvent(sB, evKV2, 0);
    attn_scores_exp<<<dim3(LV / 128, HH, HB), 256, SMEM_SC, sB>>>(Qf, Kf, Uf, Pp, HB);
    reduce_scale<<<HROW / 256, 256, 0, sB>>>(Pp + HROW * 32, scl + HROW);
    attn_pv_mma<<<dim3(8, HH, HB), 256, SMEM_PV, sB>>>(Uf, Vf, Tp, HB);
    reduce_T<<<HTHD / 256, 256, 0, sB>>>(Tp + HTHD, scl + HROW, Tf + HTHD);
    attn_out_mma<<<dim3(LV / 128, HH, HB), 256, SMEM_AO, sB>>>(Uf, Tf, Of, HB);
    cudaEventRecord(evAO2, sB);

    // ---- s0: output projection halves ----
    cudaStreamWaitEvent(s0, evQ, 0);
    cudaStreamWaitEvent(s0, evAO1, 0);
    gemm_f16<0><<<dim3(DD / 128, (HB * LV) / 256), 256, SMEM_GEMM, s0>>>(
        Of, Wt + 3 * WSZ, bo, out, nullptr, nullptr,
        HB * LV, DD, DD, DD, DD, DD, 1.0f);
    cudaStreamWaitEvent(s0, evAO2, 0);
    gemm_f16<0><<<dim3(DD / 128, (HB * LV) / 256), 256, SMEM_GEMM, s0>>>(
        Of + HVD, Wt + 3 * WSZ, bo, out + HVD, nullptr, nullptr,
        HB * LV, DD, DD, DD, DD, DD, 1.0f);
    // sB fully joined into s0 via evAO2; capture-safe.
}